// round 1
// baseline (speedup 1.0000x reference)
#include <cuda_runtime.h>

// ---------------- problem constants ----------------
#define B_     4096
#define OBS_   64
#define EP_    10
#define IN_    640      // OBS*EP
#define H_     1024
#define AD_    16
#define DP_    10
#define OUT_   160      // AD*DP
#define T_     8

#define CDECAY 0.5f
#define VTH    0.5f
#define THV   (-0.172f)
#define THU    0.529f
#define THR    0.021f
#define THS    0.132f

static const size_t NBH = (size_t)B_ * H_;     // 4,194,304
static const size_t NBO = (size_t)B_ * OUT_;   //   655,360
static const size_t NBI = (size_t)B_ * IN_;    // 2,621,440

// state layout inside g_state
#define OFF_CUR1 ((size_t)0)
#define OFF_V1   ((size_t)1 * NBH)
#define OFF_S1   ((size_t)2 * NBH)
#define OFF_R1   ((size_t)3 * NBH)
#define OFF_CUR2 ((size_t)4 * NBH)
#define OFF_V2   ((size_t)5 * NBH)
#define OFF_S2   ((size_t)6 * NBH)
#define OFF_R2   ((size_t)7 * NBH)
#define OFF_O    ((size_t)8 * NBH)
#define OFF_CURO (OFF_O + (size_t)0 * NBO)
#define OFF_VO   (OFF_O + (size_t)1 * NBO)
#define OFF_RO   (OFF_O + (size_t)2 * NBO)
#define OFF_SO0  (OFF_O + (size_t)3 * NBO)
#define OFF_SO1  (OFF_O + (size_t)4 * NBO)
#define OFF_ACC  (OFF_O + (size_t)5 * NBO)
#define STATE_TOTAL ((size_t)8 * NBH + (size_t)6 * NBO)

// ---------------- device scratch (no allocations allowed) ----------------
__device__ __align__(128) float g_spikes[(size_t)T_ * (size_t)B_ * (size_t)IN_]; // 84 MB
__device__ __align__(128) float g_x [(size_t)B_ * (size_t)H_];
__device__ __align__(128) float g_x3[(size_t)B_ * (size_t)OUT_];
__device__ __align__(128) float g_state[(size_t)8 * (size_t)B_ * (size_t)H_ + (size_t)6 * (size_t)B_ * (size_t)OUT_];

// ---------------- kernels ----------------
__global__ void zero_kernel() {
    size_t i = (size_t)blockIdx.x * blockDim.x + threadIdx.x;
    size_t stride = (size_t)gridDim.x * blockDim.x;
    for (; i < STATE_TOTAL; i += stride) g_state[i] = 0.0f;
}

// pop-encoder: compute pop_act once, unroll the 8-step integrate-and-fire
__global__ void encoder_kernel(const float* __restrict__ obs,
                               const float* __restrict__ mean,
                               const float* __restrict__ stdv) {
    int idx = blockIdx.x * blockDim.x + threadIdx.x;
    if (idx >= B_ * IN_) return;
    int b = idx / IN_;
    int i = idx - b * IN_;
    int o = i / EP_;
    float d  = obs[b * OBS_ + o] - mean[i];
    float sd = stdv[i];
    float a  = expf(-0.5f * d * d / (sd * sd));
    float volt = 0.0f;
#pragma unroll
    for (int t = 0; t < T_; t++) {
        volt += a;
        float s = volt > 1.0f ? 1.0f : 0.0f;
        volt -= s;
        g_spikes[(size_t)t * NBI + idx] = s;
    }
}

// C[m][n] = sum_k A[m][k] * W[n][k]   (A: MxK row-major, W: NxK row-major)
// 128x128 block, BK=8, 8x8 per-thread microtile, 256 threads.
__global__ __launch_bounds__(256) void sgemm_nt(const float* __restrict__ A,
                                                const float* __restrict__ W,
                                                float* __restrict__ C,
                                                int M, int N, int K) {
    const int BM = 128, BN = 128, BK = 8, TM = 8, TN = 8;
    __shared__ float As[BK][BM];
    __shared__ float Ws[BK][BN];
    const int bm = blockIdx.y * BM;
    const int bn = blockIdx.x * BN;
    const int tid  = threadIdx.x;
    const int trow = tid >> 4;      // 0..15
    const int tcol = tid & 15;      // 0..15
    const int lrow = tid >> 1;      // 0..127
    const int lcol = (tid & 1) * 4; // 0 or 4

    float acc[TM][TN];
#pragma unroll
    for (int i = 0; i < TM; i++)
#pragma unroll
        for (int j = 0; j < TN; j++) acc[i][j] = 0.0f;

    const float* Aptr = A + (size_t)(bm + lrow) * K + lcol;
    const bool wvalid = (bn + lrow) < N;
    const float* Wptr = W + (size_t)(bn + lrow) * K + lcol;

    for (int k0 = 0; k0 < K; k0 += BK) {
        float4 av = *(const float4*)(Aptr + k0);
        As[lcol + 0][lrow] = av.x; As[lcol + 1][lrow] = av.y;
        As[lcol + 2][lrow] = av.z; As[lcol + 3][lrow] = av.w;
        float4 wv = wvalid ? *(const float4*)(Wptr + k0) : make_float4(0.f, 0.f, 0.f, 0.f);
        Ws[lcol + 0][lrow] = wv.x; Ws[lcol + 1][lrow] = wv.y;
        Ws[lcol + 2][lrow] = wv.z; Ws[lcol + 3][lrow] = wv.w;
        __syncthreads();
#pragma unroll
        for (int k = 0; k < BK; k++) {
            float ar[TM], wr[TN];
#pragma unroll
            for (int i = 0; i < TM; i++) ar[i] = As[k][trow * TM + i];
#pragma unroll
            for (int j = 0; j < TN; j++) wr[j] = Ws[k][tcol * TN + j];
#pragma unroll
            for (int i = 0; i < TM; i++)
#pragma unroll
                for (int j = 0; j < TN; j++) acc[i][j] += ar[i] * wr[j];
        }
        __syncthreads();
    }
    // N is always a multiple of 4 here (1024 or 160)
#pragma unroll
    for (int i = 0; i < TM; i++) {
        int row = bm + trow * TM + i;
#pragma unroll
        for (int j = 0; j < TN; j += 4) {
            int col = bn + tcol * TN + j;
            if (col < N) {
                *(float4*)&C[(size_t)row * N + col] =
                    make_float4(acc[i][j], acc[i][j + 1], acc[i][j + 2], acc[i][j + 3]);
            }
        }
    }
}

__global__ void neuron_kernel(const float* __restrict__ x, const float* __restrict__ bias,
                              float* __restrict__ cur, float* __restrict__ v,
                              float* __restrict__ s, float* __restrict__ r,
                              int ncols, int total) {
    int idx = blockIdx.x * blockDim.x + threadIdx.x;
    if (idx >= total) return;
    int h = idx % ncols;
    float c  = cur[idx] * CDECAY + x[idx] + bias[h];
    float vv = v[idx], ss = s[idx], rr = r[idx];
    vv = vv * (1.0f - ss) + ss * THR;
    rr = rr + ss * THS;
    float vd = vv * vv - vv - rr + c;
    float rd = THV * vv - THU * rr;
    vv += vd; rr += rd;
    ss = vv > VTH ? 1.0f : 0.0f;
    cur[idx] = c; v[idx] = vv; s[idx] = ss; r[idx] = rr;
}

__global__ void neuron_out_kernel(const float* __restrict__ x, const float* __restrict__ bias,
                                  const float* __restrict__ conn_w, const float* __restrict__ conn_b,
                                  const float* __restrict__ s_prev, float* __restrict__ s_new,
                                  float* __restrict__ cur, float* __restrict__ v,
                                  float* __restrict__ r, float* __restrict__ acc) {
    int idx = blockIdx.x * blockDim.x + threadIdx.x;
    if (idx >= B_ * OUT_) return;
    int b  = idx / OUT_;
    int jg = idx - b * OUT_;
    int a  = jg / DP_;
    int j  = jg - a * DP_;
    // lateral grouped conv: lat[b,a,j] = sum_k s_prev[b,a,k] * conn_w[a,j,k] + conn_b[a,j]
    float lat = conn_b[jg];
    const float* sp = s_prev + (size_t)b * OUT_ + a * DP_;
    const float* cw = conn_w + (size_t)(a * DP_ + j) * DP_;
#pragma unroll
    for (int k = 0; k < DP_; k++) lat += sp[k] * cw[k];

    float c  = cur[idx] * CDECAY + x[idx] + bias[jg] + lat;
    float vv = v[idx], rr = r[idx], ss = s_prev[idx];
    vv = vv * (1.0f - ss) + ss * THR;
    rr = rr + ss * THS;
    float vd = vv * vv - vv - rr + c;
    float rd = THV * vv - THU * rr;
    vv += vd; rr += rd;
    ss = vv > VTH ? 1.0f : 0.0f;
    cur[idx] = c; v[idx] = vv; r[idx] = rr;
    s_new[idx] = ss;
    acc[idx] += ss;
}

__global__ void decode_kernel(const float* __restrict__ acc, const float* __restrict__ dec_w,
                              const float* __restrict__ dec_b, float* __restrict__ out) {
    int idx = blockIdx.x * blockDim.x + threadIdx.x;
    if (idx >= B_ * AD_) return;
    int b = idx / AD_;
    int a = idx - b * AD_;
    float raw = dec_b[a];
    const float* ap = acc + (size_t)b * OUT_ + a * DP_;
    const float* wp = dec_w + a * DP_;
#pragma unroll
    for (int p = 0; p < DP_; p++) raw += (ap[p] * 0.125f) * wp[p];
    out[idx] = tanhf(raw);
}

// ---------------- launch ----------------
extern "C" void kernel_launch(void* const* d_in, const int* in_sizes, int n_in,
                              void* d_out, int out_size) {
    const float* obs    = (const float*)d_in[0];
    const float* mean   = (const float*)d_in[1];
    const float* stdv   = (const float*)d_in[2];
    const float* w1     = (const float*)d_in[3];
    const float* b1     = (const float*)d_in[4];
    const float* w2     = (const float*)d_in[5];
    const float* b2     = (const float*)d_in[6];
    const float* w_out  = (const float*)d_in[7];
    const float* b_out  = (const float*)d_in[8];
    const float* conn_w = (const float*)d_in[9];
    const float* conn_b = (const float*)d_in[10];
    const float* dec_w  = (const float*)d_in[11];
    const float* dec_b  = (const float*)d_in[12];
    float* out = (float*)d_out;

    float *spikes, *x, *x3, *st;
    cudaGetSymbolAddress((void**)&spikes, g_spikes);
    cudaGetSymbolAddress((void**)&x,      g_x);
    cudaGetSymbolAddress((void**)&x3,     g_x3);
    cudaGetSymbolAddress((void**)&st,     g_state);

    zero_kernel<<<1024, 256>>>();
    encoder_kernel<<<(B_ * IN_ + 255) / 256, 256>>>(obs, mean, stdv);

    dim3 gH(H_ / 128, B_ / 128);              // (8, 32)
    dim3 gO((OUT_ + 127) / 128, B_ / 128);    // (2, 32)
    int nbhBlocks = (int)((NBH + 255) / 256);
    int nboBlocks = (int)((NBO + 255) / 256);

    for (int t = 0; t < T_; t++) {
        sgemm_nt<<<gH, 256>>>(spikes + (size_t)t * NBI, w1, x, B_, H_, IN_);
        neuron_kernel<<<nbhBlocks, 256>>>(x, b1,
            st + OFF_CUR1, st + OFF_V1, st + OFF_S1, st + OFF_R1, H_, (int)NBH);

        sgemm_nt<<<gH, 256>>>(st + OFF_S1, w2, x, B_, H_, H_);
        neuron_kernel<<<nbhBlocks, 256>>>(x, b2,
            st + OFF_CUR2, st + OFF_V2, st + OFF_S2, st + OFF_R2, H_, (int)NBH);

        sgemm_nt<<<gO, 256>>>(st + OFF_S2, w_out, x3, B_, OUT_, H_);
        float* sp = st + ((t & 1) == 0 ? OFF_SO0 : OFF_SO1);
        float* sn = st + ((t & 1) == 0 ? OFF_SO1 : OFF_SO0);
        neuron_out_kernel<<<nboBlocks, 256>>>(x3, b_out, conn_w, conn_b, sp, sn,
            st + OFF_CURO, st + OFF_VO, st + OFF_RO, st + OFF_ACC);
    }

    decode_kernel<<<(B_ * AD_ + 255) / 256, 256>>>(st + OFF_ACC, dec_w, dec_b, out);
}